// round 10
// baseline (speedup 1.0000x reference)
#include <cuda_runtime.h>
#include <cuda_fp16.h>
#include <math.h>
#include <stdint.h>

#define BB 4
#define NLN 2048
#define CC 128
#define HH 128
#define WW 128
#define NLINES (BB*NLN)   // 8192

// -------- scratch (__device__ global: allocation-free) --------
__device__ __half g_fmt_h[(size_t)BB*HH*WW*CC];   // (B,H,W,C) f16, 16.8MB

// ================= kernel 1: transpose (B,C,H,W) fp32 -> (B,H,W,C) f16 ========
__global__ void k_transpose(const float* __restrict__ fm) {
    __shared__ float tile[32][33];                 // [c][w]
    int bh = blockIdx.z;
    int b = bh >> 7, h = bh & 127;
    int c0 = blockIdx.y * 32, w0 = blockIdx.x * 32;
    int tx = threadIdx.x, ty = threadIdx.y;
    #pragma unroll
    for (int i = 0; i < 32; i += 8) {
        int c = c0 + ty + i;
        tile[ty + i][tx] = fm[(((size_t)b*CC + c)*HH + h)*WW + w0 + tx];
    }
    __syncthreads();
    int tid = ty * 32 + tx;
    #pragma unroll
    for (int it = 0; it < 2; it++) {
        int s = it * 256 + tid;
        int wi = s >> 4, cp = s & 15;
        __half2 v = __floats2half2_rn(tile[2*cp][wi], tile[2*cp+1][wi]);
        int w = w0 + wi, c = c0 + 2*cp;
        *(__half2*)&g_fmt_h[(((size_t)b*HH + h)*WW + w)*CC + c] = v;
    }
}

// ================= kernel 2: fused gather + conv stack + FC + softmax =========
// 16 lines/block, 512 threads = 16 warps.
// Gather: warp = line; lane = (parity ph, 8-ch chunk cl); shfl closes pool max.
// GEMMs: warp (mw = wid>>1, nh = wid&1): m-stripe 16 rows, n-half.
#define AS   200   // hA row stride (halves)
#define W1S  136
#define W2S  200
#define W3S  72
#define SXS  132   // sX row stride (floats)

#define OFF_W1   0
#define OFF_W2   (OFF_W1 + 64*W1S*2)
#define OFF_W3   (OFF_W2 + 64*W2S*2)
#define OFF_A    (OFF_W3 + 128*W3S*2)
#define OFF_SX   (OFF_A  + 128*AS*2)
#define OFF_FC   (OFF_SX + 128*SXS*4)
#define OFF_PAR  (OFF_FC + 4120*4)
#define SMEM_BYTES (OFF_PAR + 896*4)

__device__ __forceinline__ void mma16816(float* c, uint32_t a0, uint32_t a1,
                                         uint32_t a2, uint32_t a3,
                                         uint32_t b0, uint32_t b1) {
    asm volatile(
        "mma.sync.aligned.m16n8k16.row.col.f32.f16.f16.f32 "
        "{%0,%1,%2,%3},{%4,%5,%6,%7},{%8,%9},{%0,%1,%2,%3};"
        : "+f"(c[0]), "+f"(c[1]), "+f"(c[2]), "+f"(c[3])
        : "r"(a0), "r"(a1), "r"(a2), "r"(a3), "r"(b0), "r"(b1));
}

__global__ void __launch_bounds__(512, 1)
k_main(const float* __restrict__ lines,
       const float* __restrict__ bn1_g, const float* __restrict__ bn1_b,
       const float* __restrict__ conv1_w, const float* __restrict__ conv1_b,
       const float* __restrict__ bn2_g, const float* __restrict__ bn2_b,
       const float* __restrict__ conv2_w, const float* __restrict__ conv2_b,
       const float* __restrict__ bn3_g, const float* __restrict__ bn3_b,
       const float* __restrict__ conv3_w, const float* __restrict__ conv3_b,
       const float* __restrict__ fc2_w, const float* __restrict__ fc2_b,
       float* __restrict__ out)
{
    extern __shared__ char smem[];
    __half* hW1 = (__half*)(smem + OFF_W1);
    __half* hW2 = (__half*)(smem + OFF_W2);
    __half* hW3 = (__half*)(smem + OFF_W3);
    __half* hA  = (__half*)(smem + OFF_A);
    float*  sX  = (float*)(smem + OFF_SX);
    float*  sFC = (float*)(smem + OFF_FC);
    float*  sPar = (float*)(smem + OFF_PAR);
    float* s1  = sPar;        float* b1  = sPar + 128;
    float* c1b = sPar + 256;  float* s2  = sPar + 320;
    float* b2  = sPar + 384;  float* c2b = sPar + 448;
    float* s3  = sPar + 512;  float* b3  = sPar + 576;
    float* c3b = sPar + 640;
    float* sRed = sPar + 768;                 // [wid*8 + li*4 + i], 128 floats

    int tid = threadIdx.x;
    int wid = tid >> 5, lane = tid & 31;
    int r = lane >> 2, cq = (lane & 3) * 2;
    int mw = wid >> 1, nh = wid & 1;          // m-stripe / n-half for GEMMs
    int m0 = mw * 16;
    const float rs = rsqrtf(1.0f + 1e-5f);

    // ---- stage params + weights (f16) + fc2 ----
    if (tid < 128) {
        s1[tid] = bn1_g[tid] * rs; b1[tid] = bn1_b[tid]; c3b[tid] = conv3_b[tid];
    }
    if (tid < 64) {
        c1b[tid] = conv1_b[tid];
        s2[tid] = bn2_g[tid] * rs; b2[tid] = bn2_b[tid];
        c2b[tid] = conv2_b[tid];
        s3[tid] = bn3_g[tid] * rs; b3[tid] = bn3_b[tid];
    }
    for (int i = tid; i < 8192; i += 512) {        // W1 (64p,128c): hW1[p][c]
        int p = i >> 7, c = i & 127;
        hW1[p * W1S + c] = __float2half(conv1_w[i]);
    }
    for (int i = tid; i < 12288; i += 512) {       // W2 (64p,64q,3kk): hW2[p][kk*64+q]
        int p = i / 192, rm = i - p * 192, q = rm / 3, kk = rm - q * 3;
        hW2[p * W2S + kk * 64 + q] = __float2half(conv2_w[i]);
    }
    for (int i = tid; i < 8192; i += 512) {        // W3 (128c,64p): hW3[c][p]
        int c = i >> 6, p = i & 63;
        hW3[c * W3S + p] = __float2half(conv3_w[i]);
    }
    for (int i = tid; i < 4116; i += 512) sFC[i] = fc2_w[i];
    __syncthreads();

    // ---- gather: warp = line; lane = (ph = lane>>4, cl = lane&15) ----
    {
        int cl = lane & 15, ph = lane >> 4;
        int lnl = wid;
        int gline = blockIdx.x * 16 + lnl;
        const float* lp = lines + (size_t)gline * 4;
        float e0x = lp[0], e0y = lp[1], e1x = lp[2], e1y = lp[3];
        int bidx = gline >> 11;
        const uint4* fmt = (const uint4*)(g_fmt_h + (size_t)bidx * HH * WW * CC);

        #pragma unroll
        for (int g = 0; g < 8; g++) {
            float mx[8];
            #pragma unroll
            for (int i = 0; i < 2; i++) {
                int t = g * 4 + ph * 2 + i;
                float lam = (float)t * (1.0f / 31.0f);
                float px = e0x * lam + e1x * (1.0f - lam) - 0.5f;
                float py = e0y * lam + e1y * (1.0f - lam) - 0.5f;
                float fx0 = fminf(fmaxf(floorf(px), 0.0f), 127.0f);
                float fy0 = fminf(fmaxf(floorf(py), 0.0f), 127.0f);
                float fx1 = fminf(fx0 + 1.0f, 127.0f);
                float fy1 = fminf(fy0 + 1.0f, 127.0f);
                int x0 = (int)fx0, y0 = (int)fy0, x1 = (int)fx1, y1 = (int)fy1;
                float wa = (fx1 - px) * (fy1 - py);
                float wb = (px - fx0) * (fy1 - py);
                float wc = (fx1 - px) * (py - fy0);
                float wd = (px - fx0) * (py - fy0);
                uint4 u00 = fmt[(y0 * WW + x0) * 16 + cl];
                uint4 u10 = fmt[(y1 * WW + x0) * 16 + cl];
                uint4 u01 = fmt[(y0 * WW + x1) * 16 + cl];
                uint4 u11 = fmt[(y1 * WW + x1) * 16 + cl];
                const __half2* p00 = (const __half2*)&u00;
                const __half2* p10 = (const __half2*)&u10;
                const __half2* p01 = (const __half2*)&u01;
                const __half2* p11 = (const __half2*)&u11;
                #pragma unroll
                for (int q = 0; q < 4; q++) {
                    float2 v00 = __half22float2(p00[q]);
                    float2 v10 = __half22float2(p10[q]);
                    float2 v01 = __half22float2(p01[q]);
                    float2 v11 = __half22float2(p11[q]);
                    float sx0 = wa*v00.x + wb*v10.x + wc*v01.x + wd*v11.x;
                    float sx1 = wa*v00.y + wb*v10.y + wc*v01.y + wd*v11.y;
                    if (i == 0) { mx[2*q] = sx0; mx[2*q+1] = sx1; }
                    else { mx[2*q] = fmaxf(mx[2*q], sx0); mx[2*q+1] = fmaxf(mx[2*q+1], sx1); }
                }
            }
            // close pool group across parity partner
            #pragma unroll
            for (int q = 0; q < 8; q++)
                mx[q] = fmaxf(mx[q], __shfl_xor_sync(0xffffffffu, mx[q], 16));
            int m = lnl * 8 + g;
            int c0 = cl * 8;
            if (ph == 0) {
                *(float4*)&sX[m * SXS + c0]     = make_float4(mx[0], mx[1], mx[2], mx[3]);
                *(float4*)&sX[m * SXS + c0 + 4] = make_float4(mx[4], mx[5], mx[6], mx[7]);
            } else {
                __half2 hz[4];
                #pragma unroll
                for (int q = 0; q < 4; q++) {
                    int c = c0 + 2*q;
                    float z0 = fmaxf(s1[c]   * mx[2*q]   + b1[c],   0.0f);
                    float z1 = fmaxf(s1[c+1] * mx[2*q+1] + b1[c+1], 0.0f);
                    hz[q] = __floats2half2_rn(z0, z1);
                }
                *(uint4*)&hA[m * AS + c0] = *(uint4*)hz;
            }
        }
    }
    __syncthreads();

    // ---- GEMM1: [128m x 64n], warp does 16m x 32n (nt 0..3), 8 ksteps ----
    float acc[4][4];
    #pragma unroll
    for (int nt = 0; nt < 4; nt++) { acc[nt][0]=0; acc[nt][1]=0; acc[nt][2]=0; acc[nt][3]=0; }
    #pragma unroll
    for (int ks = 0; ks < 8; ks++) {
        int k0 = ks * 16;
        int ab = (m0 + r) * AS + k0 + cq;
        uint32_t a0 = *(const uint32_t*)&hA[ab];
        uint32_t a1 = *(const uint32_t*)&hA[ab + 8*AS];
        uint32_t a2 = *(const uint32_t*)&hA[ab + 8];
        uint32_t a3 = *(const uint32_t*)&hA[ab + 8*AS + 8];
        #pragma unroll
        for (int nt = 0; nt < 4; nt++) {
            int bb = ((nh*4 + nt)*8 + r) * W1S + k0 + cq;
            uint32_t b0v = *(const uint32_t*)&hW1[bb];
            uint32_t b1v = *(const uint32_t*)&hW1[bb + 8];
            mma16816(acc[nt], a0, a1, a2, a3, b0v, b1v);
        }
    }
    __syncthreads();

    // ---- epilogue1: im2col scatter of relu(bn2(.)) into hA[(ln,t2)][kk*64+q] ----
    for (int i = tid; i < 1024; i += 512) {
        int ln = i >> 6, q = i & 63;
        hA[(ln*8)     * AS + q]        = __float2half(0.0f);
        hA[(ln*8 + 7) * AS + 128 + q]  = __float2half(0.0f);
    }
    #pragma unroll
    for (int nt = 0; nt < 4; nt++) {
        #pragma unroll
        for (int e = 0; e < 4; e++) {
            int n = (nh*4 + nt)*8 + cq + (e & 1);
            int m_e = m0 + r + ((e >> 1) ? 8 : 0);
            float z = fmaxf(s2[n] * (acc[nt][e] + c1b[n]) + b2[n], 0.0f);
            __half hz = __float2half(z);
            int ln = m_e >> 3, t = m_e & 7;
            #pragma unroll
            for (int kk = 0; kk < 3; kk++) {
                int t2 = t + 1 - kk;
                if (t2 >= 0 && t2 < 8) hA[(ln*8 + t2) * AS + kk*64 + n] = hz;
            }
        }
    }
    __syncthreads();

    // ---- GEMM2: K=192, 12 ksteps ----
    #pragma unroll
    for (int nt = 0; nt < 4; nt++) { acc[nt][0]=0; acc[nt][1]=0; acc[nt][2]=0; acc[nt][3]=0; }
    #pragma unroll
    for (int ks = 0; ks < 12; ks++) {
        int k0 = ks * 16;
        int ab = (m0 + r) * AS + k0 + cq;
        uint32_t a0 = *(const uint32_t*)&hA[ab];
        uint32_t a1 = *(const uint32_t*)&hA[ab + 8*AS];
        uint32_t a2 = *(const uint32_t*)&hA[ab + 8];
        uint32_t a3 = *(const uint32_t*)&hA[ab + 8*AS + 8];
        #pragma unroll
        for (int nt = 0; nt < 4; nt++) {
            int bb = ((nh*4 + nt)*8 + r) * W2S + k0 + cq;
            uint32_t b0v = *(const uint32_t*)&hW2[bb];
            uint32_t b1v = *(const uint32_t*)&hW2[bb + 8];
            mma16816(acc[nt], a0, a1, a2, a3, b0v, b1v);
        }
    }
    __syncthreads();

    // ---- epilogue2: A3[m][p] = f16(relu(bn3(.))) ----
    #pragma unroll
    for (int nt = 0; nt < 4; nt++) {
        #pragma unroll
        for (int e = 0; e < 4; e++) {
            int n = (nh*4 + nt)*8 + cq + (e & 1);
            int m_e = m0 + r + ((e >> 1) ? 8 : 0);
            float z = fmaxf(s3[n] * (acc[nt][e] + c2b[n]) + b3[n], 0.0f);
            hA[m_e * AS + n] = __float2half(z);
        }
    }
    __syncthreads();

    // ---- GEMM3 (K=64): warp does 16m x 64n (nt 0..7), fused residual + FC ----
    uint32_t af[4][4];
    #pragma unroll
    for (int ks = 0; ks < 4; ks++) {
        int ab = (m0 + r) * AS + ks*16 + cq;
        af[ks][0] = *(const uint32_t*)&hA[ab];
        af[ks][1] = *(const uint32_t*)&hA[ab + 8*AS];
        af[ks][2] = *(const uint32_t*)&hA[ab + 8];
        af[ks][3] = *(const uint32_t*)&hA[ab + 8*AS + 8];
    }
    float pa0=0, pa1=0, pa2=0, pa3=0;
    float pb0=0, pb1=0, pb2=0, pb3=0;
    #pragma unroll
    for (int nt = 0; nt < 8; nt++) {
        float c4[4] = {0.f, 0.f, 0.f, 0.f};
        #pragma unroll
        for (int ks = 0; ks < 4; ks++) {
            int bb = ((nh*8 + nt)*8 + r) * W3S + ks*16 + cq;
            uint32_t b0v = *(const uint32_t*)&hW3[bb];
            uint32_t b1v = *(const uint32_t*)&hW3[bb + 8];
            mma16816(c4, af[ks][0], af[ks][1], af[ks][2], af[ks][3], b0v, b1v);
        }
        int n0e = (nh*8 + nt)*8 + cq;
        float2 x0 = *(const float2*)&sX[(m0 + r)     * SXS + n0e];
        float2 x1 = *(const float2*)&sX[(m0 + r + 8) * SXS + n0e];
        float cb0 = c3b[n0e], cb1 = c3b[n0e + 1];
        float v00 = fmaxf(x0.x + c4[0] + cb0, 0.0f);
        float v01 = fmaxf(x0.y + c4[1] + cb1, 0.0f);
        float v10 = fmaxf(x1.x + c4[2] + cb0, 0.0f);
        float v11 = fmaxf(x1.y + c4[3] + cb1, 0.0f);
        int k0i = n0e * 8 + r, k1i = k0i + 8;
        float w00 = sFC[k0i],          w01 = sFC[k1i];
        float w10 = sFC[1029 + k0i],   w11 = sFC[1029 + k1i];
        float w20 = sFC[2058 + k0i],   w21 = sFC[2058 + k1i];
        float w30 = sFC[3087 + k0i],   w31 = sFC[3087 + k1i];
        pa0 += v00*w00 + v01*w01;  pb0 += v10*w00 + v11*w01;
        pa1 += v00*w10 + v01*w11;  pb1 += v10*w10 + v11*w11;
        pa2 += v00*w20 + v01*w21;  pb2 += v10*w20 + v11*w21;
        pa3 += v00*w30 + v01*w31;  pb3 += v10*w30 + v11*w31;
    }
    #pragma unroll
    for (int off = 16; off; off >>= 1) {
        pa0 += __shfl_xor_sync(0xffffffffu, pa0, off);
        pa1 += __shfl_xor_sync(0xffffffffu, pa1, off);
        pa2 += __shfl_xor_sync(0xffffffffu, pa2, off);
        pa3 += __shfl_xor_sync(0xffffffffu, pa3, off);
        pb0 += __shfl_xor_sync(0xffffffffu, pb0, off);
        pb1 += __shfl_xor_sync(0xffffffffu, pb1, off);
        pb2 += __shfl_xor_sync(0xffffffffu, pb2, off);
        pb3 += __shfl_xor_sync(0xffffffffu, pb3, off);
    }
    if (lane < 2) {
        sRed[wid*8 + lane*4 + 0] = lane ? pb0 : pa0;
        sRed[wid*8 + lane*4 + 1] = lane ? pb1 : pa1;
        sRed[wid*8 + lane*4 + 2] = lane ? pb2 : pa2;
        sRed[wid*8 + lane*4 + 3] = lane ? pb3 : pa3;
    }
    __syncthreads();

    if (tid < 16) {
        int ln = tid;
        int mwl = ln >> 1, li = ln & 1;
        float q0 = sRed[(mwl*2)*8 + li*4 + 0] + sRed[(mwl*2+1)*8 + li*4 + 0];
        float q1 = sRed[(mwl*2)*8 + li*4 + 1] + sRed[(mwl*2+1)*8 + li*4 + 1];
        float q2 = sRed[(mwl*2)*8 + li*4 + 2] + sRed[(mwl*2+1)*8 + li*4 + 2];
        float q3 = sRed[(mwl*2)*8 + li*4 + 3] + sRed[(mwl*2+1)*8 + li*4 + 3];
        int gline = blockIdx.x * 16 + ln;
        const float* lp = lines + (size_t)gline * 4;
        float f0 = fmaxf(lp[0] * (1.0f/128.0f), 0.0f);
        float f1 = fmaxf(lp[1] * (1.0f/128.0f), 0.0f);
        float f2 = fmaxf(lp[2] * (1.0f/128.0f), 0.0f);
        float f3 = fmaxf(lp[3] * (1.0f/128.0f), 0.0f);
        float dx = lp[0] - lp[2], dy = lp[1] - lp[3];
        float f4 = fmaxf(sqrtf(dx*dx + dy*dy), 1e-6f);
        q0 += f0*sFC[1024] + f1*sFC[1025] + f2*sFC[1026] + f3*sFC[1027] + f4*sFC[1028];
        q1 += f0*sFC[1029+1024] + f1*sFC[1029+1025] + f2*sFC[1029+1026] + f3*sFC[1029+1027] + f4*sFC[1029+1028];
        q2 += f0*sFC[2058+1024] + f1*sFC[2058+1025] + f2*sFC[2058+1026] + f3*sFC[2058+1027] + f4*sFC[2058+1028];
        q3 += f0*sFC[3087+1024] + f1*sFC[3087+1025] + f2*sFC[3087+1026] + f3*sFC[3087+1027] + f4*sFC[3087+1028];
        float l0 = q0 + fc2_b[0], l1 = q1 + fc2_b[1];
        float l2 = q2 + fc2_b[2], l3 = q3 + fc2_b[3];
        float mx = fmaxf(fmaxf(l0, l1), fmaxf(l2, l3));
        float e0 = expf(l0 - mx), e1 = expf(l1 - mx);
        float e2 = expf(l2 - mx), e3 = expf(l3 - mx);
        float inv = 1.0f / (e0 + e1 + e2 + e3);
        out[(size_t)gline * 4 + 0] = l0;
        out[(size_t)gline * 4 + 1] = l1;
        out[(size_t)gline * 4 + 2] = l2;
        out[(size_t)gline * 4 + 3] = l3;
        float* pr = out + (size_t)NLINES * 4;
        pr[(size_t)gline * 4 + 0] = e0 * inv;
        pr[(size_t)gline * 4 + 1] = e1 * inv;
        pr[(size_t)gline * 4 + 2] = e2 * inv;
        pr[(size_t)gline * 4 + 3] = e3 * inv;
    }
}

// ================= launcher =================
extern "C" void kernel_launch(void* const* d_in, const int* in_sizes, int n_in,
                              void* d_out, int out_size) {
    const float* fm      = (const float*)d_in[0];
    const float* lines   = (const float*)d_in[1];
    const float* bn1_g   = (const float*)d_in[2];
    const float* bn1_b   = (const float*)d_in[3];
    const float* conv1_w = (const float*)d_in[4];
    const float* conv1_b = (const float*)d_in[5];
    const float* bn2_g   = (const float*)d_in[6];
    const float* bn2_b   = (const float*)d_in[7];
    const float* conv2_w = (const float*)d_in[8];
    const float* conv2_b = (const float*)d_in[9];
    const float* bn3_g   = (const float*)d_in[10];
    const float* bn3_b   = (const float*)d_in[11];
    const float* conv3_w = (const float*)d_in[12];
    const float* conv3_b = (const float*)d_in[13];
    const float* fc2_w   = (const float*)d_in[14];
    const float* fc2_b   = (const float*)d_in[15];
    float* out = (float*)d_out;

    static int smem_set = 0;
    if (!smem_set) {
        cudaFuncSetAttribute(k_main, cudaFuncAttributeMaxDynamicSharedMemorySize,
                             SMEM_BYTES);
        smem_set = 1;
    }

    k_transpose<<<dim3(WW / 32, CC / 32, BB * HH), dim3(32, 8)>>>(fm);
    k_main<<<NLINES / 16, 512, SMEM_BYTES>>>(
        lines, bn1_g, bn1_b, conv1_w, conv1_b, bn2_g, bn2_b,
        conv2_w, conv2_b, bn3_g, bn3_b, conv3_w, conv3_b,
        fc2_w, fc2_b, out);
}

// round 11
// speedup vs baseline: 1.5212x; 1.5212x over previous
#include <cuda_runtime.h>
#include <cuda_fp16.h>
#include <math.h>
#include <stdint.h>

#define BB 4
#define NLN 2048
#define CC 128
#define HH 128
#define WW 128
#define NLINES (BB*NLN)   // 8192

// -------- scratch (__device__ globals: allocation-free) --------
__device__ __half g_fmt_h[(size_t)BB*HH*WW*CC];   // (B,H,W,C) f16, 16.8MB

// packed f16 weight image, laid out exactly as k_main's smem weight region
#define W1S  136   // halves
#define W2S  200
#define W3S  72
#define IW1  0
#define IW2  (IW1 + 64*W1S*2)     // 17408
#define IW3  (IW2 + 64*W2S*2)     // 43008
#define IMG_BYTES (IW3 + 128*W3S*2)   // 61440
__device__ __align__(16) unsigned char g_wpack[IMG_BYTES];

// ================= kernel 1: transpose + (64 blocks) weight packing ==========
__global__ void k_transpose(const float* __restrict__ fm,
                            const float* __restrict__ conv1_w,
                            const float* __restrict__ conv2_w,
                            const float* __restrict__ conv3_w) {
    __shared__ float tile[32][33];                 // [c][w]
    int bh = blockIdx.z;
    int b = bh >> 7, h = bh & 127;
    int c0 = blockIdx.y * 32, w0 = blockIdx.x * 32;
    int tx = threadIdx.x, ty = threadIdx.y;
    #pragma unroll
    for (int i = 0; i < 32; i += 8) {
        int c = c0 + ty + i;
        tile[ty + i][tx] = fm[(((size_t)b*CC + c)*HH + h)*WW + w0 + tx];
    }
    __syncthreads();
    int tid = ty * 32 + tx;
    #pragma unroll
    for (int it = 0; it < 2; it++) {
        int s = it * 256 + tid;
        int wi = s >> 4, cp = s & 15;
        __half2 v = __floats2half2_rn(tile[2*cp][wi], tile[2*cp+1][wi]);
        int w = w0 + wi, c = c0 + 2*cp;
        *(__half2*)&g_fmt_h[(((size_t)b*HH + h)*WW + w)*CC + c] = v;
    }
    // weight packing piggyback: 64 early blocks, 16384 threads total
    if (blockIdx.x == 0 && blockIdx.y == 0 && blockIdx.z < 64) {
        int base = blockIdx.z * 256 + tid;         // 0..16383
        if (base < 8192) {                         // W1 (64p,128c) -> [p][c]
            int p = base >> 7, c = base & 127;
            ((__half*)(g_wpack + IW1))[p * W1S + c] = __float2half(conv1_w[base]);
        }
        if (base < 12288) {                        // W2 (64p,64q,3kk) -> [p][kk*64+q]
            int p = base / 192, rm = base - p * 192, q = rm / 3, kk = rm - q * 3;
            ((__half*)(g_wpack + IW2))[p * W2S + kk * 64 + q] = __float2half(conv2_w[base]);
        }
        if (base < 8192) {                         // W3 (128c,64p) -> [c][p]
            int c = base >> 6, p = base & 63;
            ((__half*)(g_wpack + IW3))[c * W3S + p] = __float2half(conv3_w[base]);
        }
    }
}

// ================= kernel 2: fused gather + conv stack + FC + softmax =========
// 8 lines/block, 256 threads = 8 warps, 2 CTAs/SM.
// Gather: warp = line; lane = (parity ph, 8-ch chunk cl).
// GEMMs: warp (mw = wid>>1, nh = wid&1): 16-row m-stripe, n-half.
#define AS   200   // hA row stride (halves)
#define SXH  136   // sX row stride (halves, f16 residual)

#define OFF_WIMG 0                              // 61440 (cp.async target)
#define OFF_A    (OFF_WIMG + IMG_BYTES)         // hA: 64*200*2 = 25600
#define OFF_SXH  (OFF_A + 64*AS*2)              // 87040, 64*136*2 = 17408
#define OFF_PAR  (OFF_SXH + 64*SXH*2)           // 104448, 768 floats
#define OFF_RED  (OFF_PAR + 768*4)              // 107520, 64 floats
#define SMEM_BYTES (OFF_RED + 64*4)             // 107776

__device__ __forceinline__ void cp_async16(uint32_t saddr, const void* g) {
    asm volatile("cp.async.cg.shared.global [%0], [%1], 16;" :: "r"(saddr), "l"(g));
}

__device__ __forceinline__ void mma16816(float* c, uint32_t a0, uint32_t a1,
                                         uint32_t a2, uint32_t a3,
                                         uint32_t b0, uint32_t b1) {
    asm volatile(
        "mma.sync.aligned.m16n8k16.row.col.f32.f16.f16.f32 "
        "{%0,%1,%2,%3},{%4,%5,%6,%7},{%8,%9},{%0,%1,%2,%3};"
        : "+f"(c[0]), "+f"(c[1]), "+f"(c[2]), "+f"(c[3])
        : "r"(a0), "r"(a1), "r"(a2), "r"(a3), "r"(b0), "r"(b1));
}

__global__ void __launch_bounds__(256, 2)
k_main(const float* __restrict__ lines,
       const float* __restrict__ bn1_g, const float* __restrict__ bn1_b,
       const float* __restrict__ conv1_b,
       const float* __restrict__ bn2_g, const float* __restrict__ bn2_b,
       const float* __restrict__ conv2_b,
       const float* __restrict__ bn3_g, const float* __restrict__ bn3_b,
       const float* __restrict__ conv3_b,
       const float* __restrict__ fc2_w, const float* __restrict__ fc2_b,
       float* __restrict__ out)
{
    extern __shared__ char smem[];
    __half* hW1 = (__half*)(smem + OFF_WIMG + IW1);
    __half* hW2 = (__half*)(smem + OFF_WIMG + IW2);
    __half* hW3 = (__half*)(smem + OFF_WIMG + IW3);
    __half* hA  = (__half*)(smem + OFF_A);
    __half* hX  = (__half*)(smem + OFF_SXH);
    float*  sPar = (float*)(smem + OFF_PAR);
    float* s1  = sPar;        float* b1  = sPar + 128;
    float* c1b = sPar + 256;  float* s2  = sPar + 320;
    float* b2  = sPar + 384;  float* c2b = sPar + 448;
    float* s3  = sPar + 512;  float* b3  = sPar + 576;
    float* c3b = sPar + 640;
    float* sRed = (float*)(smem + OFF_RED);

    int tid = threadIdx.x;
    int wid = tid >> 5, lane = tid & 31;
    int r = lane >> 2, cq = (lane & 3) * 2;
    int mw = wid >> 1, nh = wid & 1;
    int m0 = mw * 16;
    const float rs = rsqrtf(1.0f + 1e-5f);

    // ---- stage weights via cp.async (hidden behind gather) ----
    {
        uint32_t sbase = (uint32_t)__cvta_generic_to_shared(smem + OFF_WIMG);
        const unsigned char* g = g_wpack;
        for (int i = tid * 16; i < IMG_BYTES; i += 256 * 16)
            cp_async16(sbase + i, g + i);
        asm volatile("cp.async.commit_group;");
    }
    // ---- stage params (small, synchronous) ----
    if (tid < 128) {
        s1[tid] = bn1_g[tid] * rs; b1[tid] = bn1_b[tid]; c3b[tid] = conv3_b[tid];
    }
    if (tid < 64) {
        c1b[tid] = conv1_b[tid];
        s2[tid] = bn2_g[tid] * rs; b2[tid] = bn2_b[tid];
        c2b[tid] = conv2_b[tid];
        s3[tid] = bn3_g[tid] * rs; b3[tid] = bn3_b[tid];
    }
    __syncthreads();   // params visible for gather's bn1

    // ---- gather: warp = line; lane = (ph = lane>>4, cl = lane&15) ----
    {
        int cl = lane & 15, ph = lane >> 4;
        int lnl = wid;
        int gline = blockIdx.x * 8 + lnl;
        const float* lp = lines + (size_t)gline * 4;
        float e0x = lp[0], e0y = lp[1], e1x = lp[2], e1y = lp[3];
        int bidx = gline >> 11;
        const uint4* fmt = (const uint4*)(g_fmt_h + (size_t)bidx * HH * WW * CC);

        #pragma unroll
        for (int g = 0; g < 8; g++) {
            float mx[8];
            #pragma unroll
            for (int i = 0; i < 2; i++) {
                int t = g * 4 + ph * 2 + i;
                float lam = (float)t * (1.0f / 31.0f);
                float px = e0x * lam + e1x * (1.0f - lam) - 0.5f;
                float py = e0y * lam + e1y * (1.0f - lam) - 0.5f;
                float fx0 = fminf(fmaxf(floorf(px), 0.0f), 127.0f);
                float fy0 = fminf(fmaxf(floorf(py), 0.0f), 127.0f);
                float fx1 = fminf(fx0 + 1.0f, 127.0f);
                float fy1 = fminf(fy0 + 1.0f, 127.0f);
                int x0 = (int)fx0, y0 = (int)fy0, x1 = (int)fx1, y1 = (int)fy1;
                float wa = (fx1 - px) * (fy1 - py);
                float wb = (px - fx0) * (fy1 - py);
                float wc = (fx1 - px) * (py - fy0);
                float wd = (px - fx0) * (py - fy0);
                uint4 u00 = fmt[(y0 * WW + x0) * 16 + cl];
                uint4 u10 = fmt[(y1 * WW + x0) * 16 + cl];
                uint4 u01 = fmt[(y0 * WW + x1) * 16 + cl];
                uint4 u11 = fmt[(y1 * WW + x1) * 16 + cl];
                const __half2* p00 = (const __half2*)&u00;
                const __half2* p10 = (const __half2*)&u10;
                const __half2* p01 = (const __half2*)&u01;
                const __half2* p11 = (const __half2*)&u11;
                #pragma unroll
                for (int q = 0; q < 4; q++) {
                    float2 v00 = __half22float2(p00[q]);
                    float2 v10 = __half22float2(p10[q]);
                    float2 v01 = __half22float2(p01[q]);
                    float2 v11 = __half22float2(p11[q]);
                    float sx0 = wa*v00.x + wb*v10.x + wc*v01.x + wd*v11.x;
                    float sx1 = wa*v00.y + wb*v10.y + wc*v01.y + wd*v11.y;
                    if (i == 0) { mx[2*q] = sx0; mx[2*q+1] = sx1; }
                    else { mx[2*q] = fmaxf(mx[2*q], sx0); mx[2*q+1] = fmaxf(mx[2*q+1], sx1); }
                }
            }
            #pragma unroll
            for (int q = 0; q < 8; q++)
                mx[q] = fmaxf(mx[q], __shfl_xor_sync(0xffffffffu, mx[q], 16));
            int m = lnl * 8 + g;
            int c0 = cl * 8;
            if (ph == 0) {                         // residual x in f16
                __half2 hz[4];
                #pragma unroll
                for (int q = 0; q < 4; q++) hz[q] = __floats2half2_rn(mx[2*q], mx[2*q+1]);
                *(uint4*)&hX[m * SXH + c0] = *(uint4*)hz;
            } else {                               // relu(bn1(x)) in f16
                __half2 hz[4];
                #pragma unroll
                for (int q = 0; q < 4; q++) {
                    int c = c0 + 2*q;
                    float z0 = fmaxf(s1[c]   * mx[2*q]   + b1[c],   0.0f);
                    float z1 = fmaxf(s1[c+1] * mx[2*q+1] + b1[c+1], 0.0f);
                    hz[q] = __floats2half2_rn(z0, z1);
                }
                *(uint4*)&hA[m * AS + c0] = *(uint4*)hz;
            }
        }
    }
    asm volatile("cp.async.wait_group 0;");
    __syncthreads();   // gather done + weights staged

    // ---- GEMM1: [64m x 64n], warp does 16m x 32n (nt 0..3), 8 ksteps ----
    float acc[4][4];
    #pragma unroll
    for (int nt = 0; nt < 4; nt++) { acc[nt][0]=0; acc[nt][1]=0; acc[nt][2]=0; acc[nt][3]=0; }
    #pragma unroll
    for (int ks = 0; ks < 8; ks++) {
        int k0 = ks * 16;
        int ab = (m0 + r) * AS + k0 + cq;
        uint32_t a0 = *(const uint32_t*)&hA[ab];
        uint32_t a1 = *(const uint32_t*)&hA[ab + 8*AS];
        uint32_t a2 = *(const uint32_t*)&hA[ab + 8];
        uint32_t a3 = *(const uint32_t*)&hA[ab + 8*AS + 8];
        #pragma unroll
        for (int nt = 0; nt < 4; nt++) {
            int bb = ((nh*4 + nt)*8 + r) * W1S + k0 + cq;
            uint32_t b0v = *(const uint32_t*)&hW1[bb];
            uint32_t b1v = *(const uint32_t*)&hW1[bb + 8];
            mma16816(acc[nt], a0, a1, a2, a3, b0v, b1v);
        }
    }
    __syncthreads();

    // ---- epilogue1: im2col scatter of relu(bn2(.)) into hA[(ln,t2)][kk*64+q] ----
    for (int i = tid; i < 512; i += 256) {
        int ln = i >> 6, q = i & 63;
        hA[(ln*8)     * AS + q]        = __float2half(0.0f);
        hA[(ln*8 + 7) * AS + 128 + q]  = __float2half(0.0f);
    }
    #pragma unroll
    for (int nt = 0; nt < 4; nt++) {
        #pragma unroll
        for (int e = 0; e < 4; e++) {
            int n = (nh*4 + nt)*8 + cq + (e & 1);
            int m_e = m0 + r + ((e >> 1) ? 8 : 0);
            float z = fmaxf(s2[n] * (acc[nt][e] + c1b[n]) + b2[n], 0.0f);
            __half hz = __float2half(z);
            int ln = m_e >> 3, t = m_e & 7;
            #pragma unroll
            for (int kk = 0; kk < 3; kk++) {
                int t2 = t + 1 - kk;
                if (t2 >= 0 && t2 < 8) hA[(ln*8 + t2) * AS + kk*64 + n] = hz;
            }
        }
    }
    __syncthreads();

    // ---- GEMM2: K=192, 12 ksteps ----
    #pragma unroll
    for (int nt = 0; nt < 4; nt++) { acc[nt][0]=0; acc[nt][1]=0; acc[nt][2]=0; acc[nt][3]=0; }
    #pragma unroll
    for (int ks = 0; ks < 12; ks++) {
        int k0 = ks * 16;
        int ab = (m0 + r) * AS + k0 + cq;
        uint32_t a0 = *(const uint32_t*)&hA[ab];
        uint32_t a1 = *(const uint32_t*)&hA[ab + 8*AS];
        uint32_t a2 = *(const uint32_t*)&hA[ab + 8];
        uint32_t a3 = *(const uint32_t*)&hA[ab + 8*AS + 8];
        #pragma unroll
        for (int nt = 0; nt < 4; nt++) {
            int bb = ((nh*4 + nt)*8 + r) * W2S + k0 + cq;
            uint32_t b0v = *(const uint32_t*)&hW2[bb];
            uint32_t b1v = *(const uint32_t*)&hW2[bb + 8];
            mma16816(acc[nt], a0, a1, a2, a3, b0v, b1v);
        }
    }
    __syncthreads();

    // ---- epilogue2: A3[m][p] = f16(relu(bn3(.))) ----
    #pragma unroll
    for (int nt = 0; nt < 4; nt++) {
        #pragma unroll
        for (int e = 0; e < 4; e++) {
            int n = (nh*4 + nt)*8 + cq + (e & 1);
            int m_e = m0 + r + ((e >> 1) ? 8 : 0);
            float z = fmaxf(s3[n] * (acc[nt][e] + c2b[n]) + b3[n], 0.0f);
            hA[m_e * AS + n] = __float2half(z);
        }
    }
    __syncthreads();

    // ---- GEMM3 (K=64): warp does 16m x 64n (nt 0..7), fused residual + FC ----
    uint32_t af[4][4];
    #pragma unroll
    for (int ks = 0; ks < 4; ks++) {
        int ab = (m0 + r) * AS + ks*16 + cq;
        af[ks][0] = *(const uint32_t*)&hA[ab];
        af[ks][1] = *(const uint32_t*)&hA[ab + 8*AS];
        af[ks][2] = *(const uint32_t*)&hA[ab + 8];
        af[ks][3] = *(const uint32_t*)&hA[ab + 8*AS + 8];
    }
    float pa0=0, pa1=0, pa2=0, pa3=0;
    float pb0=0, pb1=0, pb2=0, pb3=0;
    #pragma unroll
    for (int nt = 0; nt < 8; nt++) {
        float c4[4] = {0.f, 0.f, 0.f, 0.f};
        #pragma unroll
        for (int ks = 0; ks < 4; ks++) {
            int bb = ((nh*8 + nt)*8 + r) * W3S + ks*16 + cq;
            uint32_t b0v = *(const uint32_t*)&hW3[bb];
            uint32_t b1v = *(const uint32_t*)&hW3[bb + 8];
            mma16816(c4, af[ks][0], af[ks][1], af[ks][2], af[ks][3], b0v, b1v);
        }
        int n0e = (nh*8 + nt)*8 + cq;
        float2 x0 = __half22float2(*(const __half2*)&hX[(m0 + r)     * SXH + n0e]);
        float2 x1 = __half22float2(*(const __half2*)&hX[(m0 + r + 8) * SXH + n0e]);
        float cb0 = c3b[n0e], cb1 = c3b[n0e + 1];
        float v00 = fmaxf(x0.x + c4[0] + cb0, 0.0f);
        float v01 = fmaxf(x0.y + c4[1] + cb1, 0.0f);
        float v10 = fmaxf(x1.x + c4[2] + cb0, 0.0f);
        float v11 = fmaxf(x1.y + c4[3] + cb1, 0.0f);
        int k0i = n0e * 8 + r, k1i = k0i + 8;
        float w00 = __ldg(&fc2_w[k0i]),        w01 = __ldg(&fc2_w[k1i]);
        float w10 = __ldg(&fc2_w[1029 + k0i]), w11 = __ldg(&fc2_w[1029 + k1i]);
        float w20 = __ldg(&fc2_w[2058 + k0i]), w21 = __ldg(&fc2_w[2058 + k1i]);
        float w30 = __ldg(&fc2_w[3087 + k0i]), w31 = __ldg(&fc2_w[3087 + k1i]);
        pa0 += v00*w00 + v01*w01;  pb0 += v10*w00 + v11*w01;
        pa1 += v00*w10 + v01*w11;  pb1 += v10*w10 + v11*w11;
        pa2 += v00*w20 + v01*w21;  pb2 += v10*w20 + v11*w21;
        pa3 += v00*w30 + v01*w31;  pb3 += v10*w30 + v11*w31;
    }
    #pragma unroll
    for (int off = 16; off; off >>= 1) {
        pa0 += __shfl_xor_sync(0xffffffffu, pa0, off);
        pa1 += __shfl_xor_sync(0xffffffffu, pa1, off);
        pa2 += __shfl_xor_sync(0xffffffffu, pa2, off);
        pa3 += __shfl_xor_sync(0xffffffffu, pa3, off);
        pb0 += __shfl_xor_sync(0xffffffffu, pb0, off);
        pb1 += __shfl_xor_sync(0xffffffffu, pb1, off);
        pb2 += __shfl_xor_sync(0xffffffffu, pb2, off);
        pb3 += __shfl_xor_sync(0xffffffffu, pb3, off);
    }
    if (lane < 2) {
        sRed[wid*8 + lane*4 + 0] = lane ? pb0 : pa0;
        sRed[wid*8 + lane*4 + 1] = lane ? pb1 : pa1;
        sRed[wid*8 + lane*4 + 2] = lane ? pb2 : pa2;
        sRed[wid*8 + lane*4 + 3] = lane ? pb3 : pa3;
    }
    __syncthreads();

    if (tid < 8) {
        int ln = tid;
        int mwl = ln >> 1, li = ln & 1;
        float q0 = sRed[(mwl*2)*8 + li*4 + 0] + sRed[(mwl*2+1)*8 + li*4 + 0];
        float q1 = sRed[(mwl*2)*8 + li*4 + 1] + sRed[(mwl*2+1)*8 + li*4 + 1];
        float q2 = sRed[(mwl*2)*8 + li*4 + 2] + sRed[(mwl*2+1)*8 + li*4 + 2];
        float q3 = sRed[(mwl*2)*8 + li*4 + 3] + sRed[(mwl*2+1)*8 + li*4 + 3];
        int gline = blockIdx.x * 8 + ln;
        const float* lp = lines + (size_t)gline * 4;
        float f0 = fmaxf(lp[0] * (1.0f/128.0f), 0.0f);
        float f1 = fmaxf(lp[1] * (1.0f/128.0f), 0.0f);
        float f2 = fmaxf(lp[2] * (1.0f/128.0f), 0.0f);
        float f3 = fmaxf(lp[3] * (1.0f/128.0f), 0.0f);
        float dx = lp[0] - lp[2], dy = lp[1] - lp[3];
        float f4 = fmaxf(sqrtf(dx*dx + dy*dy), 1e-6f);
        q0 += f0*__ldg(&fc2_w[1024]) + f1*__ldg(&fc2_w[1025]) + f2*__ldg(&fc2_w[1026]) + f3*__ldg(&fc2_w[1027]) + f4*__ldg(&fc2_w[1028]);
        q1 += f0*__ldg(&fc2_w[2053]) + f1*__ldg(&fc2_w[2054]) + f2*__ldg(&fc2_w[2055]) + f3*__ldg(&fc2_w[2056]) + f4*__ldg(&fc2_w[2057]);
        q2 += f0*__ldg(&fc2_w[3082]) + f1*__ldg(&fc2_w[3083]) + f2*__ldg(&fc2_w[3084]) + f3*__ldg(&fc2_w[3085]) + f4*__ldg(&fc2_w[3086]);
        q3 += f0*__ldg(&fc2_w[4111]) + f1*__ldg(&fc2_w[4112]) + f2*__ldg(&fc2_w[4113]) + f3*__ldg(&fc2_w[4114]) + f4*__ldg(&fc2_w[4115]);
        float l0 = q0 + fc2_b[0], l1 = q1 + fc2_b[1];
        float l2 = q2 + fc2_b[2], l3 = q3 + fc2_b[3];
        float mx = fmaxf(fmaxf(l0, l1), fmaxf(l2, l3));
        float e0 = expf(l0 - mx), e1 = expf(l1 - mx);
        float e2 = expf(l2 - mx), e3 = expf(l3 - mx);
        float inv = 1.0f / (e0 + e1 + e2 + e3);
        out[(size_t)gline * 4 + 0] = l0;
        out[(size_t)gline * 4 + 1] = l1;
        out[(size_t)gline * 4 + 2] = l2;
        out[(size_t)gline * 4 + 3] = l3;
        float* pr = out + (size_t)NLINES * 4;
        pr[(size_t)gline * 4 + 0] = e0 * inv;
        pr[(size_t)gline * 4 + 1] = e1 * inv;
        pr[(size_t)gline * 4 + 2] = e2 * inv;
        pr[(size_t)gline * 4 + 3] = e3 * inv;
    }
}

// ================= launcher =================
extern "C" void kernel_launch(void* const* d_in, const int* in_sizes, int n_in,
                              void* d_out, int out_size) {
    const float* fm      = (const float*)d_in[0];
    const float* lines   = (const float*)d_in[1];
    const float* bn1_g   = (const float*)d_in[2];
    const float* bn1_b   = (const float*)d_in[3];
    const float* conv1_w = (const float*)d_in[4];
    const float* conv1_b = (const float*)d_in[5];
    const float* bn2_g   = (const float*)d_in[6];
    const float* bn2_b   = (const float*)d_in[7];
    const float* conv2_w = (const float*)d_in[8];
    const float* conv2_b = (const float*)d_in[9];
    const float* bn3_g   = (const float*)d_in[10];
    const float* bn3_b   = (const float*)d_in[11];
    const float* conv3_w = (const float*)d_in[12];
    const float* conv3_b = (const float*)d_in[13];
    const float* fc2_w   = (const float*)d_in[14];
    const float* fc2_b   = (const float*)d_in[15];
    float* out = (float*)d_out;

    static int smem_set = 0;
    if (!smem_set) {
        cudaFuncSetAttribute(k_main, cudaFuncAttributeMaxDynamicSharedMemorySize,
                             SMEM_BYTES);
        smem_set = 1;
    }

    k_transpose<<<dim3(WW / 32, CC / 32, BB * HH), dim3(32, 8)>>>(fm, conv1_w, conv2_w, conv3_w);
    k_main<<<NLINES / 8, 256, SMEM_BYTES>>>(
        lines, bn1_g, bn1_b, conv1_b, bn2_g, bn2_b, conv2_b,
        bn3_g, bn3_b, conv3_b, fc2_w, fc2_b, out);
}

// round 16
// speedup vs baseline: 1.6766x; 1.1021x over previous
#include <cuda_runtime.h>
#include <cuda_fp16.h>
#include <math.h>
#include <stdint.h>

#define BB 4
#define NLN 2048
#define CC 128
#define HH 128
#define WW 128
#define NLINES (BB*NLN)   // 8192

// -------- scratch (__device__ globals: allocation-free) --------
__device__ __half g_fmt_h[(size_t)BB*HH*WW*CC];   // (B,H,W,C) f16, 16.8MB

// packed f16 weight image, laid out exactly as k_main's smem weight region
#define W1S  136   // halves
#define W2S  200
#define W3S  72
#define IW1  0
#define IW2  (IW1 + 64*W1S*2)     // 17408
#define IW3  (IW2 + 64*W2S*2)     // 43008
#define IMG_BYTES (IW3 + 128*W3S*2)   // 61440
__device__ __align__(16) unsigned char g_wpack[IMG_BYTES];

// ================= kernel 1: transpose + (64 blocks) weight packing ==========
__global__ void k_transpose(const float* __restrict__ fm,
                            const float* __restrict__ conv1_w,
                            const float* __restrict__ conv2_w,
                            const float* __restrict__ conv3_w) {
    __shared__ float tile[32][33];                 // [c][w]
    int bh = blockIdx.z;
    int b = bh >> 7, h = bh & 127;
    int c0 = blockIdx.y * 32, w0 = blockIdx.x * 32;
    int tx = threadIdx.x, ty = threadIdx.y;
    #pragma unroll
    for (int i = 0; i < 32; i += 8) {
        int c = c0 + ty + i;
        tile[ty + i][tx] = fm[(((size_t)b*CC + c)*HH + h)*WW + w0 + tx];
    }
    __syncthreads();
    int tid = ty * 32 + tx;
    #pragma unroll
    for (int it = 0; it < 2; it++) {
        int s = it * 256 + tid;
        int wi = s >> 4, cp = s & 15;
        __half2 v = __floats2half2_rn(tile[2*cp][wi], tile[2*cp+1][wi]);
        int w = w0 + wi, c = c0 + 2*cp;
        *(__half2*)&g_fmt_h[(((size_t)b*HH + h)*WW + w)*CC + c] = v;
    }
    // weight packing piggyback: 64 early blocks
    if (blockIdx.x == 0 && blockIdx.y == 0 && blockIdx.z < 64) {
        int base = blockIdx.z * 256 + tid;         // 0..16383
        if (base < 8192) {                         // W1 (64p,128c) -> [p][c]
            int p = base >> 7, c = base & 127;
            ((__half*)(g_wpack + IW1))[p * W1S + c] = __float2half(conv1_w[base]);
        }
        if (base < 12288) {                        // W2 (64p,64q,3kk) -> [p][kk*64+q]
            int p = base / 192, rm = base - p * 192, q = rm / 3, kk = rm - q * 3;
            ((__half*)(g_wpack + IW2))[p * W2S + kk * 64 + q] = __float2half(conv2_w[base]);
        }
        if (base < 8192) {                         // W3 (128c,64p) -> [c][p]
            int c = base >> 6, p = base & 63;
            ((__half*)(g_wpack + IW3))[c * W3S + p] = __float2half(conv3_w[base]);
        }
    }
}

// ================= kernel 2: fused gather + conv stack + FC + softmax =========
// 8 lines/block, 256 threads = 8 warps, 2 CTAs/SM.
#define AS   200   // hA row stride (halves)
#define SXH  136   // hX row stride (halves)

#define OFF_WIMG 0
#define OFF_A    (OFF_WIMG + IMG_BYTES)
#define OFF_SXH  (OFF_A + 64*AS*2)
#define OFF_PAR  (OFF_SXH + 64*SXH*2)
#define OFF_RED  (OFF_PAR + 768*4)
#define SMEM_BYTES (OFF_RED + 64*4)   // 107776

__device__ __forceinline__ void cp_async16(uint32_t saddr, const void* g) {
    asm volatile("cp.async.cg.shared.global [%0], [%1], 16;" :: "r"(saddr), "l"(g));
}
__device__ __forceinline__ void mma16816(float* c, uint32_t a0, uint32_t a1,
                                         uint32_t a2, uint32_t a3,
                                         uint32_t b0, uint32_t b1) {
    asm volatile(
        "mma.sync.aligned.m16n8k16.row.col.f32.f16.f16.f32 "
        "{%0,%1,%2,%3},{%4,%5,%6,%7},{%8,%9},{%0,%1,%2,%3};"
        : "+f"(c[0]), "+f"(c[1]), "+f"(c[2]), "+f"(c[3])
        : "r"(a0), "r"(a1), "r"(a2), "r"(a3), "r"(b0), "r"(b1));
}
__device__ __forceinline__ void ldmx4(uint32_t& a0, uint32_t& a1, uint32_t& a2,
                                      uint32_t& a3, uint32_t addr) {
    asm volatile("ldmatrix.sync.aligned.m8n8.x4.shared.b16 {%0,%1,%2,%3}, [%4];"
                 : "=r"(a0), "=r"(a1), "=r"(a2), "=r"(a3) : "r"(addr));
}
__device__ __forceinline__ void ldmx2(uint32_t& b0, uint32_t& b1, uint32_t addr) {
    asm volatile("ldmatrix.sync.aligned.m8n8.x2.shared.b16 {%0,%1}, [%2];"
                 : "=r"(b0), "=r"(b1) : "r"(addr));
}
__device__ __forceinline__ __half2 shmax2(__half2 m) {
    uint32_t v = *(uint32_t*)&m;
    uint32_t p = __shfl_xor_sync(0xffffffffu, v, 16);
    return __hmax2(m, *(__half2*)&p);
}

__global__ void __launch_bounds__(256, 2)
k_main(const float* __restrict__ lines,
       const float* __restrict__ bn1_g, const float* __restrict__ bn1_b,
       const float* __restrict__ conv1_b,
       const float* __restrict__ bn2_g, const float* __restrict__ bn2_b,
       const float* __restrict__ conv2_b,
       const float* __restrict__ bn3_g, const float* __restrict__ bn3_b,
       const float* __restrict__ conv3_b,
       const float* __restrict__ fc2_w, const float* __restrict__ fc2_b,
       float* __restrict__ out)
{
    extern __shared__ char smem[];
    __half* hW1 = (__half*)(smem + OFF_WIMG + IW1);
    __half* hW2 = (__half*)(smem + OFF_WIMG + IW2);
    __half* hW3 = (__half*)(smem + OFF_WIMG + IW3);
    __half* hA  = (__half*)(smem + OFF_A);
    __half* hX  = (__half*)(smem + OFF_SXH);
    float*  sPar = (float*)(smem + OFF_PAR);
    uint32_t* s1h = (uint32_t*)sPar;          // 64 half2
    uint32_t* b1h = (uint32_t*)(sPar + 64);   // 64 half2
    float* c1b = sPar + 128;  float* s2  = sPar + 192;
    float* b2  = sPar + 256;  float* c2b = sPar + 320;
    float* s3  = sPar + 384;  float* b3  = sPar + 448;
    float* c3b = sPar + 512;                  // 128
    float* sRed = (float*)(smem + OFF_RED);

    int tid = threadIdx.x;
    int wid = tid >> 5, lane = tid & 31;
    int r = lane >> 2, cq = (lane & 3) * 2;
    int mw = wid >> 1, nh = wid & 1;
    int m0 = mw * 16;
    const float rs = rsqrtf(1.0f + 1e-5f);

    // ---- stage weights via cp.async (hidden behind gather) ----
    {
        uint32_t sbase = (uint32_t)__cvta_generic_to_shared(smem + OFF_WIMG);
        const unsigned char* g = g_wpack;
        for (int i = tid * 16; i < IMG_BYTES; i += 256 * 16)
            cp_async16(sbase + i, g + i);
        asm volatile("cp.async.commit_group;");
    }
    // ---- stage params ----
    if (tid < 64) {
        __half2 hg = __floats2half2_rn(bn1_g[2*tid] * rs, bn1_g[2*tid+1] * rs);
        s1h[tid] = *(uint32_t*)&hg;
        __half2 hb = __floats2half2_rn(bn1_b[2*tid], bn1_b[2*tid+1]);
        b1h[tid] = *(uint32_t*)&hb;
        c1b[tid] = conv1_b[tid];
        s2[tid] = bn2_g[tid] * rs; b2[tid] = bn2_b[tid];
        c2b[tid] = conv2_b[tid];
        s3[tid] = bn3_g[tid] * rs; b3[tid] = bn3_b[tid];
    }
    if (tid < 128) c3b[tid] = conv3_b[tid];
    __syncthreads();

    // ---- gather: warp = line; lane = (ph = lane>>4, cl = lane&15), half2 math ----
    {
        int cl = lane & 15, ph = lane >> 4;
        int lnl = wid;
        int gline = blockIdx.x * 8 + lnl;
        const float* lp = lines + (size_t)gline * 4;
        float e0x = lp[0], e0y = lp[1], e1x = lp[2], e1y = lp[3];
        int bidx = gline >> 11;
        const uint4* fmt = (const uint4*)(g_fmt_h + (size_t)bidx * HH * WW * CC);

        #pragma unroll
        for (int g = 0; g < 8; g++) {
            uint4 u[2][4];
            __half2 wt[2][4];
            #pragma unroll
            for (int i = 0; i < 2; i++) {
                int t = g * 4 + ph * 2 + i;
                float lam = (float)t * (1.0f / 31.0f);
                float px = e0x * lam + e1x * (1.0f - lam) - 0.5f;
                float py = e0y * lam + e1y * (1.0f - lam) - 0.5f;
                float fx0 = fminf(fmaxf(floorf(px), 0.0f), 127.0f);
                float fy0 = fminf(fmaxf(floorf(py), 0.0f), 127.0f);
                float fx1 = fminf(fx0 + 1.0f, 127.0f);
                float fy1 = fminf(fy0 + 1.0f, 127.0f);
                int x0 = (int)fx0, y0 = (int)fy0, x1 = (int)fx1, y1 = (int)fy1;
                wt[i][0] = __float2half2_rn((fx1 - px) * (fy1 - py));
                wt[i][1] = __float2half2_rn((px - fx0) * (fy1 - py));
                wt[i][2] = __float2half2_rn((fx1 - px) * (py - fy0));
                wt[i][3] = __float2half2_rn((px - fx0) * (py - fy0));
                u[i][0] = fmt[(y0 * WW + x0) * 16 + cl];
                u[i][1] = fmt[(y1 * WW + x0) * 16 + cl];
                u[i][2] = fmt[(y0 * WW + x1) * 16 + cl];
                u[i][3] = fmt[(y1 * WW + x1) * 16 + cl];
            }
            __half2 mxh[4];
            #pragma unroll
            for (int i = 0; i < 2; i++) {
                const __half2* p0 = (const __half2*)&u[i][0];
                const __half2* p1 = (const __half2*)&u[i][1];
                const __half2* p2 = (const __half2*)&u[i][2];
                const __half2* p3 = (const __half2*)&u[i][3];
                #pragma unroll
                for (int q = 0; q < 4; q++) {
                    __half2 s = __hmul2(wt[i][0], p0[q]);
                    s = __hfma2(wt[i][1], p1[q], s);
                    s = __hfma2(wt[i][2], p2[q], s);
                    s = __hfma2(wt[i][3], p3[q], s);
                    mxh[q] = (i == 0) ? s : __hmax2(mxh[q], s);
                }
            }
            #pragma unroll
            for (int q = 0; q < 4; q++) mxh[q] = shmax2(mxh[q]);
            int m = lnl * 8 + g;
            int c0 = cl * 8;
            if (ph == 0) {                         // residual x (f16)
                *(uint4*)&hX[m * SXH + c0] = *(uint4*)mxh;
            } else {                               // relu(bn1(x)) (f16)
                __half2 zero2 = __float2half2_rn(0.0f);
                __half2 hz[4];
                #pragma unroll
                for (int q = 0; q < 4; q++) {
                    int ci = cl * 4 + q;
                    __half2 sc = *(__half2*)&s1h[ci];
                    __half2 bi = *(__half2*)&b1h[ci];
                    hz[q] = __hmax2(__hfma2(sc, mxh[q], bi), zero2);
                }
                *(uint4*)&hA[m * AS + c0] = *(uint4*)hz;
            }
        }
    }
    asm volatile("cp.async.wait_group 0;");
    __syncthreads();

    // ldmatrix lane-address components
    uint32_t uA = (uint32_t)__cvta_generic_to_shared(hA);
    uint32_t aBase = uA + (uint32_t)(((m0 + (lane & 7) + ((lane >> 3) & 1) * 8) * AS
                                      + ((lane >> 4) & 1) * 8) * 2);
    int bro = (lane & 7);                      // b-row offset within tile
    int bco = ((lane >> 3) & 1) * 8;           // b k-col offset (lanes 8-15 -> +8)

    // ---- GEMM1: warp 16m x 32n (nt 0..3), 8 ksteps ----
    float acc[4][4];
    #pragma unroll
    for (int nt = 0; nt < 4; nt++) { acc[nt][0]=0; acc[nt][1]=0; acc[nt][2]=0; acc[nt][3]=0; }
    {
        uint32_t uW1 = (uint32_t)__cvta_generic_to_shared(hW1);
        uint32_t bBase = uW1 + (uint32_t)((((nh*4)*8 + bro) * W1S + bco) * 2);
        #pragma unroll
        for (int ks = 0; ks < 8; ks++) {
            uint32_t a0, a1, a2, a3;
            ldmx4(a0, a1, a2, a3, aBase + ks * 32);
            #pragma unroll
            for (int nt = 0; nt < 4; nt++) {
                uint32_t b0v, b1v;
                ldmx2(b0v, b1v, bBase + nt * (8 * W1S * 2) + ks * 32);
                mma16816(acc[nt], a0, a1, a2, a3, b0v, b1v);
            }
        }
    }
    __syncthreads();

    // ---- epilogue1: im2col scatter of relu(bn2(.)) ----
    for (int i = tid; i < 512; i += 256) {
        int ln = i >> 6, q = i & 63;
        hA[(ln*8)     * AS + q]        = __float2half(0.0f);
        hA[(ln*8 + 7) * AS + 128 + q]  = __float2half(0.0f);
    }
    #pragma unroll
    for (int nt = 0; nt < 4; nt++) {
        #pragma unroll
        for (int e = 0; e < 4; e++) {
            int n = (nh*4 + nt)*8 + cq + (e & 1);
            int m_e = m0 + r + ((e >> 1) ? 8 : 0);
            float z = fmaxf(s2[n] * (acc[nt][e] + c1b[n]) + b2[n], 0.0f);
            __half hz = __float2half(z);
            int ln = m_e >> 3, t = m_e & 7;
            #pragma unroll
            for (int kk = 0; kk < 3; kk++) {
                int t2 = t + 1 - kk;
                if (t2 >= 0 && t2 < 8) hA[(ln*8 + t2) * AS + kk*64 + n] = hz;
            }
        }
    }
    __syncthreads();

    // ---- GEMM2: K=192, 12 ksteps ----
    #pragma unroll
    for (int nt = 0; nt < 4; nt++) { acc[nt][0]=0; acc[nt][1]=0; acc[nt][2]=0; acc[nt][3]=0; }
    {
        uint32_t uW2 = (uint32_t)__cvta_generic_to_shared(hW2);
        uint32_t bBase = uW2 + (uint32_t)((((nh*4)*8 + bro) * W2S + bco) * 2);
        #pragma unroll
        for (int ks = 0; ks < 12; ks++) {
            uint32_t a0, a1, a2, a3;
            ldmx4(a0, a1, a2, a3, aBase + ks * 32);
            #pragma unroll
            for (int nt = 0; nt < 4; nt++) {
                uint32_t b0v, b1v;
                ldmx2(b0v, b1v, bBase + nt * (8 * W2S * 2) + ks * 32);
                mma16816(acc[nt], a0, a1, a2, a3, b0v, b1v);
            }
        }
    }
    __syncthreads();

    // ---- epilogue2: A3[m][p] = f16(relu(bn3(.))) ----
    #pragma unroll
    for (int nt = 0; nt < 4; nt++) {
        #pragma unroll
        for (int e = 0; e < 4; e++) {
            int n = (nh*4 + nt)*8 + cq + (e & 1);
            int m_e = m0 + r + ((e >> 1) ? 8 : 0);
            float z = fmaxf(s3[n] * (acc[nt][e] + c2b[n]) + b3[n], 0.0f);
            hA[m_e * AS + n] = __float2half(z);
        }
    }
    __syncthreads();

    // ---- GEMM3 (K=64): warp 16m x 64n (nt 0..7), fused residual + FC ----
    uint32_t af[4][4];
    #pragma unroll
    for (int ks = 0; ks < 4; ks++)
        ldmx4(af[ks][0], af[ks][1], af[ks][2], af[ks][3], aBase + ks * 32);
    float pa0=0, pa1=0, pa2=0, pa3=0;
    float pb0=0, pb1=0, pb2=0, pb3=0;
    {
        uint32_t uW3 = (uint32_t)__cvta_generic_to_shared(hW3);
        uint32_t bBase = uW3 + (uint32_t)((((nh*8)*8 + bro) * W3S + bco) * 2);
        #pragma unroll
        for (int nt = 0; nt < 8; nt++) {
            float c4[4] = {0.f, 0.f, 0.f, 0.f};
            #pragma unroll
            for (int ks = 0; ks < 4; ks++) {
                uint32_t b0v, b1v;
                ldmx2(b0v, b1v, bBase + nt * (8 * W3S * 2) + ks * 32);
                mma16816(c4, af[ks][0], af[ks][1], af[ks][2], af[ks][3], b0v, b1v);
            }
            int n0e = (nh*8 + nt)*8 + cq;
            float2 x0 = __half22float2(*(const __half2*)&hX[(m0 + r)     * SXH + n0e]);
            float2 x1 = __half22float2(*(const __half2*)&hX[(m0 + r + 8) * SXH + n0e]);
            float cb0 = c3b[n0e], cb1 = c3b[n0e + 1];
            float v00 = fmaxf(x0.x + c4[0] + cb0, 0.0f);
            float v01 = fmaxf(x0.y + c4[1] + cb1, 0.0f);
            float v10 = fmaxf(x1.x + c4[2] + cb0, 0.0f);
            float v11 = fmaxf(x1.y + c4[3] + cb1, 0.0f);
            int k0i = n0e * 8 + r, k1i = k0i + 8;
            float w00 = __ldg(&fc2_w[k0i]),        w01 = __ldg(&fc2_w[k1i]);
            float w10 = __ldg(&fc2_w[1029 + k0i]), w11 = __ldg(&fc2_w[1029 + k1i]);
            float w20 = __ldg(&fc2_w[2058 + k0i]), w21 = __ldg(&fc2_w[2058 + k1i]);
            float w30 = __ldg(&fc2_w[3087 + k0i]), w31 = __ldg(&fc2_w[3087 + k1i]);
            pa0 += v00*w00 + v01*w01;  pb0 += v10*w00 + v11*w01;
            pa1 += v00*w10 + v01*w11;  pb1 += v10*w10 + v11*w11;
            pa2 += v00*w20 + v01*w21;  pb2 += v10*w20 + v11*w21;
            pa3 += v00*w30 + v01*w31;  pb3 += v10*w30 + v11*w31;
        }
    }
    #pragma unroll
    for (int off = 16; off; off >>= 1) {
        pa0 += __shfl_xor_sync(0xffffffffu, pa0, off);
        pa1 += __shfl_xor_sync(0xffffffffu, pa1, off);
        pa2 += __shfl_xor_sync(0xffffffffu, pa2, off);
        pa3 += __shfl_xor_sync(0xffffffffu, pa3, off);
        pb0 += __shfl_xor_sync(0xffffffffu, pb0, off);
        pb1 += __shfl_xor_sync(0xffffffffu, pb1, off);
        pb2 += __shfl_xor_sync(0xffffffffu, pb2, off);
        pb3 += __shfl_xor_sync(0xffffffffu, pb3, off);
    }
    if (lane < 2) {
        sRed[wid*8 + lane*4 + 0] = lane ? pb0 : pa0;
        sRed[wid*8 + lane*4 + 1] = lane ? pb1 : pa1;
        sRed[wid*8 + lane*4 + 2] = lane ? pb2 : pa2;
        sRed[wid*8 + lane*4 + 3] = lane ? pb3 : pa3;
    }
    __syncthreads();

    if (tid < 8) {
        int ln = tid;
        int mwl = ln >> 1, li = ln & 1;
        float q0 = sRed[(mwl*2)*8 + li*4 + 0] + sRed[(mwl*2+1)*8 + li*4 + 0];
        float q1 = sRed[(mwl*2)*8 + li*4 + 1] + sRed[(mwl*2+1)*8 + li*4 + 1];
        float q2 = sRed[(mwl*2)*8 + li*4 + 2] + sRed[(mwl*2+1)*8 + li*4 + 2];
        float q3 = sRed[(mwl*2)*8 + li*4 + 3] + sRed[(mwl*2+1)*8 + li*4 + 3];
        int gline = blockIdx.x * 8 + ln;
        const float* lp = lines + (size_t)gline * 4;
        float f0 = fmaxf(lp[0] * (1.0f/128.0f), 0.0f);
        float f1 = fmaxf(lp[1] * (1.0f/128.0f), 0.0f);
        float f2 = fmaxf(lp[2] * (1.0f/128.0f), 0.0f);
        float f3 = fmaxf(lp[3] * (1.0f/128.0f), 0.0f);
        float dx = lp[0] - lp[2], dy = lp[1] - lp[3];
        float f4 = fmaxf(sqrtf(dx*dx + dy*dy), 1e-6f);
        q0 += f0*__ldg(&fc2_w[1024]) + f1*__ldg(&fc2_w[1025]) + f2*__ldg(&fc2_w[1026]) + f3*__ldg(&fc2_w[1027]) + f4*__ldg(&fc2_w[1028]);
        q1 += f0*__ldg(&fc2_w[2053]) + f1*__ldg(&fc2_w[2054]) + f2*__ldg(&fc2_w[2055]) + f3*__ldg(&fc2_w[2056]) + f4*__ldg(&fc2_w[2057]);
        q2 += f0*__ldg(&fc2_w[3082]) + f1*__ldg(&fc2_w[3083]) + f2*__ldg(&fc2_w[3084]) + f3*__ldg(&fc2_w[3085]) + f4*__ldg(&fc2_w[3086]);
        q3 += f0*__ldg(&fc2_w[4111]) + f1*__ldg(&fc2_w[4112]) + f2*__ldg(&fc2_w[4113]) + f3*__ldg(&fc2_w[4114]) + f4*__ldg(&fc2_w[4115]);
        float l0 = q0 + fc2_b[0], l1 = q1 + fc2_b[1];
        float l2 = q2 + fc2_b[2], l3 = q3 + fc2_b[3];
        float mx = fmaxf(fmaxf(l0, l1), fmaxf(l2, l3));
        float e0 = expf(l0 - mx), e1 = expf(l1 - mx);
        float e2 = expf(l2 - mx), e3 = expf(l3 - mx);
        float inv = 1.0f / (e0 + e1 + e2 + e3);
        out[(size_t)gline * 4 + 0] = l0;
        out[(size_t)gline * 4 + 1] = l1;
        out[(size_t)gline * 4 + 2] = l2;
        out[(size_t)gline * 4 + 3] = l3;
        float* pr = out + (size_t)NLINES * 4;
        pr[(size_t)gline * 4 + 0] = e0 * inv;
        pr[(size_t)gline * 4 + 1] = e1 * inv;
        pr[(size_t)gline * 4 + 2] = e2 * inv;
        pr[(size_t)gline * 4 + 3] = e3 * inv;
    }
}

// ================= launcher =================
extern "C" void kernel_launch(void* const* d_in, const int* in_sizes, int n_in,
                              void* d_out, int out_size) {
    const float* fm      = (const float*)d_in[0];
    const float* lines   = (const float*)d_in[1];
    const float* bn1_g   = (const float*)d_in[2];
    const float* bn1_b   = (const float*)d_in[3];
    const float* conv1_w = (const float*)d_in[4];
    const float* conv1_b = (const float*)d_in[5];
    const float* bn2_g   = (const float*)d_in[6];
    const float* bn2_b   = (const float*)d_in[7];
    const float* conv2_w = (const float*)d_in[8];
    const float* conv2_b = (const float*)d_in[9];
    const float* bn3_g   = (const float*)d_in[10];
    const float* bn3_b   = (const float*)d_in[11];
    const float* conv3_w = (const float*)d_in[12];
    const float* conv3_b = (const float*)d_in[13];
    const float* fc2_w   = (const float*)d_in[14];
    const float* fc2_b   = (const float*)d_in[15];
    float* out = (float*)d_out;

    static int smem_set = 0;
    if (!smem_set) {
        cudaFuncSetAttribute(k_main, cudaFuncAttributeMaxDynamicSharedMemorySize,
                             SMEM_BYTES);
        smem_set = 1;
    }

    k_transpose<<<dim3(WW / 32, CC / 32, BB * HH), dim3(32, 8)>>>(fm, conv1_w, conv2_w, conv3_w);
    k_main<<<NLINES / 8, 256, SMEM_BYTES>>>(
        lines, bn1_g, bn1_b, conv1_b, bn2_g, bn2_b, conv2_b,
        bn3_g, bn3_b, conv3_b, fc2_w, fc2_b, out);
}